// round 3
// baseline (speedup 1.0000x reference)
#include <cuda_runtime.h>
#include <math.h>

#define E_TOTAL   65536      // B*N*K = 2*1024*32
#define EDGE_DIM  32
#define MIDC      256
#define PCOLS     768        // SPLIT_SZ = NF*MI*MO
#define W3_LD     1536
#define W3_OFF    768        // SPLIT_OFF

// ---- scratch (static device globals; no allocations) ----
__device__ float g_h1[(size_t)E_TOTAL * MIDC];   // 64 MB
__device__ float g_h2[(size_t)E_TOTAL * MIDC];   // 64 MB
__device__ float g_rp[(size_t)E_TOTAL * PCOLS];  // 192 MB

__device__ __forceinline__ float gelu_exact(float x) {
    // jax.nn.gelu(approximate=False): 0.5*x*(1+erf(x/sqrt(2)))
    return 0.5f * x * (1.0f + erff(x * 0.70710678118654752f));
}

// ============================================================
// Kernel 1: h1 = gelu(edges[E,32] @ W1[32,256] + b1)
// 64 edges per block, 256 threads; thread owns one output column.
// ============================================================
__global__ __launch_bounds__(256) void k1_mlp1(
    const float* __restrict__ edges, const float* __restrict__ W1,
    const float* __restrict__ b1)
{
    __shared__ float es[64][33];      // padded
    __shared__ float W1s[32][256];
    const int tid = threadIdx.x;
    const long e0 = (long)blockIdx.x * 64;

    #pragma unroll
    for (int i = 0; i < 8; i++) {                       // 64*32 = 2048 floats
        int flat = tid + i * 256;
        es[flat >> 5][flat & 31] = edges[e0 * EDGE_DIM + flat];
    }
    #pragma unroll
    for (int i = 0; i < 32; i++) {                      // 32*256 = 8192 floats
        int flat = tid + i * 256;
        W1s[flat >> 8][flat & 255] = W1[flat];
    }
    __syncthreads();

    const int m = tid;
    const float bm = b1[m];
    for (int e = 0; e < 64; e++) {
        float acc = bm;
        #pragma unroll
        for (int k = 0; k < EDGE_DIM; k++)
            acc = fmaf(es[e][k], W1s[k][m], acc);
        g_h1[(e0 + e) * MIDC + m] = gelu_exact(acc);
    }
}

// ============================================================
// Generic 64x256 output-tile GEMM: C[e, cb+n] = act(A[e,:256] @ W[:, wcol0+cb+n] (+bias))
//   A: [E,256] row-major (from g_h1 or g_h2)
//   W: row stride ws, columns offset wcol0 + blockIdx.y*256
//   Per-thread 8x8 register tile; A staged in 64KB dynamic smem (broadcast reads);
//   W streamed via L1 (8 warps share the same 256KB chunk per block).
// ============================================================
template <bool DOGELU>
__global__ __launch_bounds__(256) void k_gemm256(
    const float* __restrict__ A, const float* __restrict__ W,
    const float* __restrict__ bias, float* __restrict__ C,
    int ws, int wcol0, int ldc)
{
    extern __shared__ float As[];     // [64][256] = 64KB
    const int tid = threadIdx.x;
    const long e0 = (long)blockIdx.x * 64;
    const int cb = blockIdx.y * 256;

    #pragma unroll
    for (int i = 0; i < 64; i++) {                      // 64*256 floats
        int flat = tid + i * 256;
        As[flat] = A[e0 * MIDC + flat];
    }
    __syncthreads();

    const int tm = tid & 31;
    const int te = tid >> 5;

    float acc[8][8];
    #pragma unroll
    for (int j = 0; j < 8; j++) {
        float bv = (bias != nullptr) ? bias[cb + tm + 32 * j] : 0.0f;
        #pragma unroll
        for (int i = 0; i < 8; i++) acc[i][j] = bv;
    }

    const float* Wp = W + (size_t)(wcol0 + cb) + tm;

    #pragma unroll 2
    for (int k = 0; k < 256; k++) {
        float a[8], w[8];
        #pragma unroll
        for (int i = 0; i < 8; i++) a[i] = As[(te * 8 + i) * 256 + k];  // broadcast LDS
        #pragma unroll
        for (int j = 0; j < 8; j++) w[j] = Wp[(size_t)k * ws + 32 * j]; // coalesced, L1-hot
        #pragma unroll
        for (int i = 0; i < 8; i++)
            #pragma unroll
            for (int j = 0; j < 8; j++)
                acc[i][j] = fmaf(a[i], w[j], acc[i][j]);
    }

    #pragma unroll
    for (int i = 0; i < 8; i++) {
        const long e = e0 + te * 8 + i;
        #pragma unroll
        for (int j = 0; j < 8; j++) {
            float v = acc[i][j];
            if (DOGELU) v = gelu_exact(v);
            C[e * (long)ldc + cb + tm + 32 * j] = v;
        }
    }
}

// ============================================================
// Kernel 4: per-edge  tmp = feats@basis (reshaped), out = rw @ tmp
//   16 edges/block, 256 threads. Thread (e,o) computes out[e,o,0..2].
// ============================================================
__global__ __launch_bounds__(256) void k4_contract(
    const float* __restrict__ feats, const float* __restrict__ basis,
    float* __restrict__ out)
{
    __shared__ float tmps[16][48][3];
    const int tid = threadIdx.x;
    const long e0 = (long)blockIdx.x * 16;

    // tmp[e, i*3 + z/3, z%3] = sum_din feats[e,i,din] * basis[e,din,z]   (z in [0,9))
    for (int flat = tid; flat < 16 * 144; flat += 256) {
        int e = flat / 144;
        int r = flat % 144;
        int i = r / 9;
        int z = r % 9;
        long eg = e0 + e;
        float v = 0.0f;
        #pragma unroll
        for (int din = 0; din < 3; din++)
            v = fmaf(feats[eg * 48 + i * 3 + din], basis[eg * 27 + din * 9 + z], v);
        tmps[e][i * 3 + z / 3][z % 3] = v;
    }
    __syncthreads();

    const int e = tid >> 4;
    const int o = tid & 15;
    const long eg = e0 + e;
    const float4* rp4 = reinterpret_cast<const float4*>(g_rp + eg * PCOLS + o * 48);

    float a0 = 0.f, a1 = 0.f, a2 = 0.f;
    #pragma unroll
    for (int jj = 0; jj < 12; jj++) {
        float4 rv = rp4[jj];
        int j = jj * 4;
        a0 = fmaf(rv.x, tmps[e][j + 0][0], a0);
        a1 = fmaf(rv.x, tmps[e][j + 0][1], a1);
        a2 = fmaf(rv.x, tmps[e][j + 0][2], a2);
        a0 = fmaf(rv.y, tmps[e][j + 1][0], a0);
        a1 = fmaf(rv.y, tmps[e][j + 1][1], a1);
        a2 = fmaf(rv.y, tmps[e][j + 1][2], a2);
        a0 = fmaf(rv.z, tmps[e][j + 2][0], a0);
        a1 = fmaf(rv.z, tmps[e][j + 2][1], a1);
        a2 = fmaf(rv.z, tmps[e][j + 2][2], a2);
        a0 = fmaf(rv.w, tmps[e][j + 3][0], a0);
        a1 = fmaf(rv.w, tmps[e][j + 3][1], a1);
        a2 = fmaf(rv.w, tmps[e][j + 3][2], a2);
    }
    float* op = out + eg * 48 + o * 3;
    op[0] = a0; op[1] = a1; op[2] = a2;
}

// ============================================================
extern "C" void kernel_launch(void* const* d_in, const int* in_sizes, int n_in,
                              void* d_out, int out_size)
{
    const float* edges = (const float*)d_in[0];
    const float* feats = (const float*)d_in[1];
    const float* basis = (const float*)d_in[2];
    const float* W1    = (const float*)d_in[3];
    const float* b1    = (const float*)d_in[4];
    const float* W2    = (const float*)d_in[5];
    const float* b2    = (const float*)d_in[6];
    const float* W3    = (const float*)d_in[7];
    float* out = (float*)d_out;

    float *h1p, *h2p, *rpp;
    cudaGetSymbolAddress((void**)&h1p, g_h1);
    cudaGetSymbolAddress((void**)&h2p, g_h2);
    cudaGetSymbolAddress((void**)&rpp, g_rp);

    const int SMEM = 64 * 256 * sizeof(float);  // 64KB dynamic
    cudaFuncSetAttribute(k_gemm256<true>,  cudaFuncAttributeMaxDynamicSharedMemorySize, SMEM);
    cudaFuncSetAttribute(k_gemm256<false>, cudaFuncAttributeMaxDynamicSharedMemorySize, SMEM);

    // 1) h1 = gelu(edges @ W1 + b1)
    k1_mlp1<<<E_TOTAL / 64, 256>>>(edges, W1, b1);

    // 2) h2 = gelu(h1 @ W2 + b2)
    k_gemm256<true><<<dim3(E_TOTAL / 64, 1), 256, SMEM>>>(
        h1p, W2, b2, h2p, MIDC, 0, MIDC);

    // 3) rp_k = h2 @ W3[:, 768:1536]   (only the used 768 columns)
    k_gemm256<false><<<dim3(E_TOTAL / 64, 3), 256, SMEM>>>(
        h2p, W3, nullptr, rpp, W3_LD, W3_OFF, PCOLS);

    // 4) out = rw @ (feats @ basis)
    k4_contract<<<E_TOTAL / 16, 256>>>(feats, basis, out);
}

// round 7
// speedup vs baseline: 1.2931x; 1.2931x over previous
#include <cuda_runtime.h>
#include <math.h>

typedef unsigned long long ull;

#define E_TOTAL   65536      // B*N*K = 2*1024*32
#define EDGE_DIM  32
#define MIDC      256
#define PCOLS     768        // SPLIT_SZ = NF*MI*MO
#define W3_LD     1536
#define W3_OFF    768        // SPLIT_OFF

// ---- scratch (static device globals; no allocations) ----
__device__ float g_h1[(size_t)E_TOTAL * MIDC];   // 64 MB
__device__ float g_h2[(size_t)E_TOTAL * MIDC];   // 64 MB
__device__ float g_rp[(size_t)E_TOTAL * PCOLS];  // 192 MB

__device__ __forceinline__ float gelu_exact(float x) {
    // jax.nn.gelu(approximate=False): 0.5*x*(1+erf(x/sqrt(2)))
    return 0.5f * x * (1.0f + erff(x * 0.70710678118654752f));
}

// ---- packed f32x2 helpers (FFMA2 path; only reachable via PTX) ----
__device__ __forceinline__ ull pack2(float lo, float hi) {
    ull r; asm("mov.b64 %0, {%1, %2};" : "=l"(r) : "f"(lo), "f"(hi)); return r;
}
__device__ __forceinline__ ull dup2(float x) {
    ull r; asm("mov.b64 %0, {%1, %1};" : "=l"(r) : "f"(x)); return r;
}
__device__ __forceinline__ ull fma2(ull a, ull b, ull c) {
    ull d; asm("fma.rn.f32x2 %0, %1, %2, %3;" : "=l"(d) : "l"(a), "l"(b), "l"(c)); return d;
}
__device__ __forceinline__ float2 unpack2(ull v) {
    float2 f; asm("mov.b64 {%0, %1}, %2;" : "=f"(f.x), "=f"(f.y) : "l"(v)); return f;
}

// ============================================================
// Kernel 1: h1 = gelu(edges[E,32] @ W1[32,256] + b1)
// 64 edges/block, 256 threads; thread owns one output column,
// processes 2 edges at a time via f32x2 (edges transposed in smem).
// ============================================================
__global__ __launch_bounds__(256) void k1_mlp1(
    const float* __restrict__ edges, const float* __restrict__ W1,
    const float* __restrict__ b1)
{
    __shared__ float esT[32][64];     // [k][e] — edge pairs contiguous
    __shared__ float W1s[32][256];
    const int tid = threadIdx.x;
    const long e0 = (long)blockIdx.x * 64;

    #pragma unroll
    for (int i = 0; i < 8; i++) {                       // 64*32 = 2048 floats
        int flat = tid + i * 256;
        esT[flat & 31][flat >> 5] = edges[e0 * EDGE_DIM + flat];
    }
    #pragma unroll
    for (int i = 0; i < 32; i++) {                      // 32*256 = 8192 floats
        int flat = tid + i * 256;
        W1s[flat >> 8][flat & 255] = W1[flat];
    }
    __syncthreads();

    const int m = tid;
    ull wd[EDGE_DIM];
    #pragma unroll
    for (int k = 0; k < EDGE_DIM; k++) wd[k] = dup2(W1s[k][m]);
    const ull binit = dup2(b1[m]);

    for (int p = 0; p < 32; p++) {    // 32 edge-pairs
        ull acc = binit;
        #pragma unroll
        for (int k = 0; k < EDGE_DIM; k++) {
            ull a2 = reinterpret_cast<const ull*>(&esT[k][0])[p];  // broadcast LDS.64
            acc = fma2(a2, wd[k], acc);
        }
        float2 v = unpack2(acc);
        g_h1[(e0 + 2 * p)     * MIDC + m] = gelu_exact(v.x);
        g_h1[(e0 + 2 * p + 1) * MIDC + m] = gelu_exact(v.y);
    }
}

// ============================================================
// Generic 64x256 output-tile GEMM with packed f32x2 accumulation:
//   C[e, cb+c] = act(A[e,:256] @ W[:, wcol0+cb+c] (+bias))
//   Thread owns 8 edges x 4 column-PAIRS (8x8 scalar tile, FFMA2-packed).
//   A staged in 64KB dynamic smem (broadcast LDS); W via coalesced LDG.64, L1-hot.
// ============================================================
template <bool DOGELU>
__global__ __launch_bounds__(256) void k_gemm256(
    const float* __restrict__ A, const float* __restrict__ W,
    const float* __restrict__ bias, float* __restrict__ C,
    int ws, int wcol0, int ldc)
{
    extern __shared__ float As[];     // [64][256] = 64KB
    const int tid = threadIdx.x;
    const long e0 = (long)blockIdx.x * 64;
    const int cb = blockIdx.y * 256;

    // vectorized A stage (rows contiguous since A is [E,256] row-major)
    {
        const float4* Ag = reinterpret_cast<const float4*>(A + e0 * MIDC);
        float4* As4 = reinterpret_cast<float4*>(As);
        #pragma unroll
        for (int i = 0; i < 16; i++) As4[tid + i * 256] = Ag[tid + i * 256];
    }
    __syncthreads();

    const int tm = tid & 31;          // column-pair group
    const int te = tid >> 5;          // edge group
    const int col0 = cb + 2 * tm;     // thread's columns: col0 + 64*jp (+1)

    ull acc[8][4];
    #pragma unroll
    for (int jp = 0; jp < 4; jp++) {
        ull binit = (bias != nullptr)
            ? pack2(bias[col0 + 64 * jp], bias[col0 + 64 * jp + 1])
            : 0ULL;
        #pragma unroll
        for (int i = 0; i < 8; i++) acc[i][jp] = binit;
    }

    const float* Wbase = W + (size_t)wcol0 + col0;

    #pragma unroll 2
    for (int k = 0; k < 256; k++) {
        ull a2[8], w2[4];
        #pragma unroll
        for (int i = 0; i < 8; i++) a2[i] = dup2(As[(te * 8 + i) * 256 + k]);
        const ull* wr = reinterpret_cast<const ull*>(Wbase + (size_t)k * ws);
        #pragma unroll
        for (int jp = 0; jp < 4; jp++) w2[jp] = wr[32 * jp];   // LDG.64, coalesced
        #pragma unroll
        for (int i = 0; i < 8; i++)
            #pragma unroll
            for (int jp = 0; jp < 4; jp++)
                acc[i][jp] = fma2(a2[i], w2[jp], acc[i][jp]);
    }

    #pragma unroll
    for (int i = 0; i < 8; i++) {
        const long e = e0 + te * 8 + i;
        float* Crow = C + e * (long)ldc + col0;
        #pragma unroll
        for (int jp = 0; jp < 4; jp++) {
            float2 v = unpack2(acc[i][jp]);
            if (DOGELU) { v.x = gelu_exact(v.x); v.y = gelu_exact(v.y); }
            *reinterpret_cast<float2*>(Crow + 64 * jp) = v;    // STG.64
        }
    }
}

// ============================================================
// Kernel 4: per-edge  tmp = feats@basis (reshaped), out = rw @ tmp
//   16 edges/block, 256 threads. Thread (e,o) computes out[e,o,0..2].
// ============================================================
__global__ __launch_bounds__(256) void k4_contract(
    const float* __restrict__ feats, const float* __restrict__ basis,
    float* __restrict__ out)
{
    __shared__ float tmps[16][48][3];
    const int tid = threadIdx.x;
    const long e0 = (long)blockIdx.x * 16;

    // tmp[e, i*3 + z/3, z%3] = sum_din feats[e,i,din] * basis[e,din,z]   (z in [0,9))
    for (int flat = tid; flat < 16 * 144; flat += 256) {
        int e = flat / 144;
        int r = flat % 144;
        int i = r / 9;
        int z = r % 9;
        long eg = e0 + e;
        float v = 0.0f;
        #pragma unroll
        for (int din = 0; din < 3; din++)
            v = fmaf(feats[eg * 48 + i * 3 + din], basis[eg * 27 + din * 9 + z], v);
        tmps[e][i * 3 + z / 3][z % 3] = v;
    }
    __syncthreads();

    const int e = tid >> 4;
    const int o = tid & 15;
    const long eg = e0 + e;
    const float4* rp4 = reinterpret_cast<const float4*>(g_rp + eg * PCOLS + o * 48);

    float a0 = 0.f, a1 = 0.f, a2 = 0.f;
    #pragma unroll
    for (int jj = 0; jj < 12; jj++) {
        float4 rv = rp4[jj];
        int j = jj * 4;
        a0 = fmaf(rv.x, tmps[e][j + 0][0], a0);
        a1 = fmaf(rv.x, tmps[e][j + 0][1], a1);
        a2 = fmaf(rv.x, tmps[e][j + 0][2], a2);
        a0 = fmaf(rv.y, tmps[e][j + 1][0], a0);
        a1 = fmaf(rv.y, tmps[e][j + 1][1], a1);
        a2 = fmaf(rv.y, tmps[e][j + 1][2], a2);
        a0 = fmaf(rv.z, tmps[e][j + 2][0], a0);
        a1 = fmaf(rv.z, tmps[e][j + 2][1], a1);
        a2 = fmaf(rv.z, tmps[e][j + 2][2], a2);
        a0 = fmaf(rv.w, tmps[e][j + 3][0], a0);
        a1 = fmaf(rv.w, tmps[e][j + 3][1], a1);
        a2 = fmaf(rv.w, tmps[e][j + 3][2], a2);
    }
    float* op = out + eg * 48 + o * 3;
    op[0] = a0; op[1] = a1; op[2] = a2;
}

// ============================================================
extern "C" void kernel_launch(void* const* d_in, const int* in_sizes, int n_in,
                              void* d_out, int out_size)
{
    const float* edges = (const float*)d_in[0];
    const float* feats = (const float*)d_in[1];
    const float* basis = (const float*)d_in[2];
    const float* W1    = (const float*)d_in[3];
    const float* b1    = (const float*)d_in[4];
    const float* W2    = (const float*)d_in[5];
    const float* b2    = (const float*)d_in[6];
    const float* W3    = (const float*)d_in[7];
    float* out = (float*)d_out;

    float *h1p, *h2p, *rpp;
    cudaGetSymbolAddress((void**)&h1p, g_h1);
    cudaGetSymbolAddress((void**)&h2p, g_h2);
    cudaGetSymbolAddress((void**)&rpp, g_rp);

    const int SMEM = 64 * 256 * sizeof(float);  // 64KB dynamic
    cudaFuncSetAttribute(k_gemm256<true>,  cudaFuncAttributeMaxDynamicSharedMemorySize, SMEM);
    cudaFuncSetAttribute(k_gemm256<false>, cudaFuncAttributeMaxDynamicSharedMemorySize, SMEM);

    // 1) h1 = gelu(edges @ W1 + b1)
    k1_mlp1<<<E_TOTAL / 64, 256>>>(edges, W1, b1);

    // 2) h2 = gelu(h1 @ W2 + b2)
    k_gemm256<true><<<dim3(E_TOTAL / 64, 1), 256, SMEM>>>(
        h1p, W2, b2, h2p, MIDC, 0, MIDC);

    // 3) rp_k = h2 @ W3[:, 768:1536]   (only the used 768 columns)
    k_gemm256<false><<<dim3(E_TOTAL / 64, 3), 256, SMEM>>>(
        h2p, W3, nullptr, rpp, W3_LD, W3_OFF, PCOLS);

    // 4) out = rw @ (feats @ basis)
    k4_contract<<<E_TOTAL / 16, 256>>>(feats, basis, out);
}

// round 11
// speedup vs baseline: 1.7569x; 1.3587x over previous
#include <cuda_runtime.h>
#include <cuda_bf16.h>
#include <math.h>
#include <stdint.h>

typedef unsigned long long ull;

#define E_TOTAL   65536      // B*N*K = 2*1024*32
#define EDGE_DIM  32
#define MIDC      256
#define PCOLS     768        // SPLIT_SZ = NF*MI*MO
#define W3_LD     1536
#define W3_OFF    768        // SPLIT_OFF

// ---- scratch (static device globals; no allocations) ----
__device__ unsigned short g_h1h[(size_t)E_TOTAL * MIDC];   // bf16 hi of gelu(mlp1)
__device__ unsigned short g_h1l[(size_t)E_TOTAL * MIDC];   // bf16 lo
__device__ unsigned short g_h2h[(size_t)E_TOTAL * MIDC];
__device__ unsigned short g_h2l[(size_t)E_TOTAL * MIDC];
__device__ unsigned short g_w2h[256 * 256];                // W2^T [n][k]
__device__ unsigned short g_w2l[256 * 256];
__device__ unsigned short g_w3h[768 * 256];                // W3k^T [n][k]
__device__ unsigned short g_w3l[768 * 256];
__device__ float g_rp[(size_t)E_TOTAL * PCOLS];            // 192 MB

__device__ __forceinline__ float gelu_exact(float x) {
    return 0.5f * x * (1.0f + erff(x * 0.70710678118654752f));
}

// ---- fp32 -> bf16 hi/lo split ----
__device__ __forceinline__ void split2(float x, unsigned short& h, unsigned short& l) {
    __nv_bfloat16 bh = __float2bfloat16_rn(x);
    float r = x - __bfloat162float(bh);
    __nv_bfloat16 bl = __float2bfloat16_rn(r);
    h = __bfloat16_as_ushort(bh);
    l = __bfloat16_as_ushort(bl);
}

// ---- packed f32x2 helpers (k1 only) ----
__device__ __forceinline__ ull dup2(float x) {
    ull r; asm("mov.b64 %0, {%1, %1};" : "=l"(r) : "f"(x)); return r;
}
__device__ __forceinline__ ull fma2(ull a, ull b, ull c) {
    ull d; asm("fma.rn.f32x2 %0, %1, %2, %3;" : "=l"(d) : "l"(a), "l"(b), "l"(c)); return d;
}
__device__ __forceinline__ float2 unpack2(ull v) {
    float2 f; asm("mov.b64 {%0, %1}, %2;" : "=f"(f.x), "=f"(f.y) : "l"(v)); return f;
}

// ---- warp-MMA helpers (baseline PTX ISA — valid on sm_103 base target) ----
__device__ __forceinline__ uint32_t smem_u32(const void* p) {
    uint32_t a;
    asm("{ .reg .u64 t; cvta.to.shared.u64 t, %1; cvt.u32.u64 %0, t; }" : "=r"(a) : "l"(p));
    return a;
}
__device__ __forceinline__ void ldm4(uint32_t* r, uint32_t addr) {
    asm volatile("ldmatrix.sync.aligned.m8n8.x4.shared.b16 {%0,%1,%2,%3}, [%4];"
                 : "=r"(r[0]), "=r"(r[1]), "=r"(r[2]), "=r"(r[3]) : "r"(addr));
}
__device__ __forceinline__ void mma16816(float* c, const uint32_t* a, const uint32_t* b) {
    asm volatile(
        "mma.sync.aligned.m16n8k16.row.col.f32.bf16.bf16.f32 "
        "{%0,%1,%2,%3}, {%4,%5,%6,%7}, {%8,%9}, {%0,%1,%2,%3};"
        : "+f"(c[0]), "+f"(c[1]), "+f"(c[2]), "+f"(c[3])
        : "r"(a[0]), "r"(a[1]), "r"(a[2]), "r"(a[3]), "r"(b[0]), "r"(b[1]));
}

// ============================================================
// Kernel 0: transpose + split weights to bf16 hi/lo, K-major
// ============================================================
__global__ __launch_bounds__(256) void k_prep_w(
    const float* __restrict__ W2, const float* __restrict__ W3)
{
    int idx = blockIdx.x * 256 + threadIdx.x;   // 1024 blocks -> 262144
    if (idx < 256 * 256) {
        int k = idx >> 8, n = idx & 255;
        unsigned short h, l;
        split2(W2[k * 256 + n], h, l);
        g_w2h[n * 256 + k] = h;
        g_w2l[n * 256 + k] = l;
    } else {
        int j = idx - 256 * 256;                // 196608 elements
        int k = j / 768, n = j % 768;
        unsigned short h, l;
        split2(W3[k * W3_LD + W3_OFF + n], h, l);
        g_w3h[n * 256 + k] = h;
        g_w3l[n * 256 + k] = l;
    }
}

// ============================================================
// Kernel 1: h1 = gelu(edges[E,32] @ W1 + b1), output bf16 hi/lo
// ============================================================
__global__ __launch_bounds__(256) void k1_mlp1(
    const float* __restrict__ edges, const float* __restrict__ W1,
    const float* __restrict__ b1)
{
    __shared__ float esT[32][64];     // [k][e]
    __shared__ float W1s[32][256];
    const int tid = threadIdx.x;
    const long e0 = (long)blockIdx.x * 64;

    #pragma unroll
    for (int i = 0; i < 8; i++) {
        int flat = tid + i * 256;
        esT[flat & 31][flat >> 5] = edges[e0 * EDGE_DIM + flat];
    }
    #pragma unroll
    for (int i = 0; i < 32; i++) {
        int flat = tid + i * 256;
        W1s[flat >> 8][flat & 255] = W1[flat];
    }
    __syncthreads();

    const int m = tid;
    ull wd[EDGE_DIM];
    #pragma unroll
    for (int k = 0; k < EDGE_DIM; k++) wd[k] = dup2(W1s[k][m]);
    const ull binit = dup2(b1[m]);

    for (int p = 0; p < 32; p++) {
        ull acc = binit;
        #pragma unroll
        for (int k = 0; k < EDGE_DIM; k++) {
            ull a2 = reinterpret_cast<const ull*>(&esT[k][0])[p];
            acc = fma2(a2, wd[k], acc);
        }
        float2 v = unpack2(acc);
        unsigned short h, l;
        size_t o0 = (size_t)(e0 + 2 * p) * MIDC + m;
        split2(gelu_exact(v.x), h, l);
        g_h1h[o0] = h; g_h1l[o0] = l;
        split2(gelu_exact(v.y), h, l);
        g_h1h[o0 + MIDC] = h; g_h1l[o0 + MIDC] = l;
    }
}

// ============================================================
// bf16-split warp-MMA GEMM: C[128e x 128n], K=256 in 4 chunks of 64.
//   A[e][k] row-major hi/lo;  W[n][k] row-major (== k-major col layout) hi/lo
//   D = Ah@Bh + Ah@Bl + Al@Bh  (fp32 accum in registers via mma.sync)
//   GELU=true : C = gelu(D + bias) -> bf16 hi/lo (ld 256)
//   GELU=false: C = D -> fp32 (ld = ldcf)
// grid (n_tiles, E/128), 256 threads = 8 warps (4m x 2n), warp tile 32x64.
// ============================================================
#define KC    64
#define PADB  176                              // padded row stride in bytes (64*2 data + 48)
#define TILEB (128 * PADB)                     // 22528
#define SOFF_BIAS 0                            // 512 B
#define SOFF_AH   512
#define SOFF_AL   (512 + TILEB)
#define SOFF_BH   (512 + 2 * TILEB)
#define SOFF_BL   (512 + 3 * TILEB)
#define SMEM_GEMM (512 + 4 * TILEB)            // 90624 B

template <bool GELU>
__global__ __launch_bounds__(256) void k_mma_gemm(
    const unsigned short* __restrict__ Ah, const unsigned short* __restrict__ Al,
    const unsigned short* __restrict__ Wh, const unsigned short* __restrict__ Wl,
    const float* __restrict__ bias,
    unsigned short* __restrict__ Ch, unsigned short* __restrict__ Cl,
    float* __restrict__ Cf, int ldcf)
{
    extern __shared__ char sm[];
    const uint32_t smb = smem_u32(sm);
    const int tid = threadIdx.x;
    const int wid = tid >> 5;
    const int l   = tid & 31;
    const int wm  = wid >> 1;       // 0..3  (m block of 32)
    const int wn  = wid & 1;        // 0..1  (n block of 64)
    const long e0 = (long)blockIdx.y * 128;
    const int n0  = blockIdx.x * 128;
    float* bias_s = reinterpret_cast<float*>(sm + SOFF_BIAS);

    if (GELU && tid < 128) bias_s[tid] = bias[n0 + tid];

    // ---- staging geometry: thread loads 4x16B per tile ----
    const int srow = tid >> 1;                 // 0..127
    const int sseg = tid & 1;                  // half-row (32 elems = 64B)
    const size_t gAr = (size_t)(e0 + srow) * 256 + sseg * 32;
    const size_t gBr = (size_t)(n0 + srow) * 256 + sseg * 32;
    char* s_ah = sm + SOFF_AH + srow * PADB + sseg * 64;
    char* s_al = sm + SOFF_AL + srow * PADB + sseg * 64;
    char* s_bh = sm + SOFF_BH + srow * PADB + sseg * 64;
    char* s_bl = sm + SOFF_BL + srow * PADB + sseg * 64;

    // ---- ldmatrix base addresses (within-tile, chunk-invariant) ----
    // A frag x4: lanes 0-15 -> rows m0..15 @k0, lanes 16-31 -> same rows @k+8
    const int arow0 = wm * 32 + (l & 15);
    const uint32_t aoff = (uint32_t)arow0 * PADB + ((l >> 4) * 16);
    const uint32_t aAH0 = smb + SOFF_AH + aoff;
    const uint32_t aAH1 = aAH0 + 16 * PADB;
    const uint32_t aAL0 = smb + SOFF_AL + aoff;
    const uint32_t aAL1 = aAL0 + 16 * PADB;
    // B frag x4: m0:n0-7@k0, m1:n0-7@k8, m2:n8-15@k0, m3:n8-15@k8
    const int brow_in16 = ((l & 16) >> 1) + (l & 7);
    const uint32_t bkoff = (l & 8) ? 16u : 0u;
    uint32_t aBH[4], aBL[4];
    #pragma unroll
    for (int p = 0; p < 4; p++) {
        uint32_t ro = (uint32_t)(wn * 64 + p * 16 + brow_in16) * PADB + bkoff;
        aBH[p] = smb + SOFF_BH + ro;
        aBL[p] = smb + SOFF_BL + ro;
    }

    float acc[2][8][4];
    #pragma unroll
    for (int mi = 0; mi < 2; mi++)
        #pragma unroll
        for (int ng = 0; ng < 8; ng++)
            #pragma unroll
            for (int t = 0; t < 4; t++) acc[mi][ng][t] = 0.0f;

    for (int c = 0; c < 4; c++) {
        const int k0 = c * KC;
        // ---- stage A/B hi+lo (16B vector copies) ----
        if (c) __syncthreads();
        #pragma unroll
        for (int i = 0; i < 4; i++) {
            uint4 va = *reinterpret_cast<const uint4*>(Ah + gAr + k0 + i * 8);
            uint4 vb = *reinterpret_cast<const uint4*>(Al + gAr + k0 + i * 8);
            uint4 vc = *reinterpret_cast<const uint4*>(Wh + gBr + k0 + i * 8);
            uint4 vd = *reinterpret_cast<const uint4*>(Wl + gBr + k0 + i * 8);
            *reinterpret_cast<uint4*>(s_ah + i * 16) = va;
            *reinterpret_cast<uint4*>(s_al + i * 16) = vb;
            *reinterpret_cast<uint4*>(s_bh + i * 16) = vc;
            *reinterpret_cast<uint4*>(s_bl + i * 16) = vd;
        }
        __syncthreads();

        #pragma unroll
        for (int ks = 0; ks < 4; ks++) {
            const uint32_t kb = ks * 32;       // 16 k-elems = 32B
            uint32_t ahf[2][4], alf[2][4];
            ldm4(ahf[0], aAH0 + kb);
            ldm4(ahf[1], aAH1 + kb);
            ldm4(alf[0], aAL0 + kb);
            ldm4(alf[1], aAL1 + kb);
            #pragma unroll
            for (int p = 0; p < 4; p++) {
                uint32_t bhf[4], blf[4];
                ldm4(bhf, aBH[p] + kb);
                ldm4(blf, aBL[p] + kb);
                #pragma unroll
                for (int mi = 0; mi < 2; mi++) {
                    mma16816(acc[mi][2 * p],     ahf[mi], bhf);
                    mma16816(acc[mi][2 * p + 1], ahf[mi], bhf + 2);
                    mma16816(acc[mi][2 * p],     ahf[mi], blf);
                    mma16816(acc[mi][2 * p + 1], ahf[mi], blf + 2);
                    mma16816(acc[mi][2 * p],     alf[mi], bhf);
                    mma16816(acc[mi][2 * p + 1], alf[mi], bhf + 2);
                }
            }
        }
    }

    // ---- epilogue: c-frag (row = l/4 (+8), col = 2*(l%4) (+1)) ----
    const int crow = wm * 32 + (l >> 2);
    const int ccol = wn * 64 + 2 * (l & 3);
    #pragma unroll
    for (int mi = 0; mi < 2; mi++) {
        #pragma unroll
        for (int ng = 0; ng < 8; ng++) {
            const int col = ccol + ng * 8;     // local col (even)
            const float* cf = acc[mi][ng];
            #pragma unroll
            for (int half = 0; half < 2; half++) {
                const long e = e0 + crow + mi * 16 + half * 8;
                float x0 = cf[2 * half + 0];
                float x1 = cf[2 * half + 1];
                if (GELU) {
                    x0 = gelu_exact(x0 + bias_s[col]);
                    x1 = gelu_exact(x1 + bias_s[col + 1]);
                    unsigned short h0, l0, h1, l1;
                    split2(x0, h0, l0);
                    split2(x1, h1, l1);
                    *reinterpret_cast<uint32_t*>(Ch + (size_t)e * MIDC + n0 + col) =
                        (uint32_t)h0 | ((uint32_t)h1 << 16);
                    *reinterpret_cast<uint32_t*>(Cl + (size_t)e * MIDC + n0 + col) =
                        (uint32_t)l0 | ((uint32_t)l1 << 16);
                } else {
                    float2 v; v.x = x0; v.y = x1;
                    *reinterpret_cast<float2*>(Cf + (size_t)e * ldcf + n0 + col) = v;
                }
            }
        }
    }
}

// ============================================================
// Kernel 4: per-edge  tmp = feats@basis, out = rw @ tmp
// ============================================================
__global__ __launch_bounds__(256) void k4_contract(
    const float* __restrict__ feats, const float* __restrict__ basis,
    float* __restrict__ out)
{
    __shared__ float tmps[16][48][3];
    const int tid = threadIdx.x;
    const long e0 = (long)blockIdx.x * 16;

    for (int flat = tid; flat < 16 * 144; flat += 256) {
        int e = flat / 144;
        int r = flat % 144;
        int i = r / 9;
        int z = r % 9;
        long eg = e0 + e;
        float v = 0.0f;
        #pragma unroll
        for (int din = 0; din < 3; din++)
            v = fmaf(feats[eg * 48 + i * 3 + din], basis[eg * 27 + din * 9 + z], v);
        tmps[e][i * 3 + z / 3][z % 3] = v;
    }
    __syncthreads();

    const int e = tid >> 4;
    const int o = tid & 15;
    const long eg = e0 + e;
    const float4* rp4 = reinterpret_cast<const float4*>(g_rp + eg * PCOLS + o * 48);

    float a0 = 0.f, a1 = 0.f, a2 = 0.f;
    #pragma unroll
    for (int jj = 0; jj < 12; jj++) {
        float4 rv = rp4[jj];
        int j = jj * 4;
        a0 = fmaf(rv.x, tmps[e][j + 0][0], a0);
        a1 = fmaf(rv.x, tmps[e][j + 0][1], a1);
        a2 = fmaf(rv.x, tmps[e][j + 0][2], a2);
        a0 = fmaf(rv.y, tmps[e][j + 1][0], a0);
        a1 = fmaf(rv.y, tmps[e][j + 1][1], a1);
        a2 = fmaf(rv.y, tmps[e][j + 1][2], a2);
        a0 = fmaf(rv.z, tmps[e][j + 2][0], a0);
        a1 = fmaf(rv.z, tmps[e][j + 2][1], a1);
        a2 = fmaf(rv.z, tmps[e][j + 2][2], a2);
        a0 = fmaf(rv.w, tmps[e][j + 3][0], a0);
        a1 = fmaf(rv.w, tmps[e][j + 3][1], a1);
        a2 = fmaf(rv.w, tmps[e][j + 3][2], a2);
    }
    float* op = out + eg * 48 + o * 3;
    op[0] = a0; op[1] = a1; op[2] = a2;
}

// ============================================================
extern "C" void kernel_launch(void* const* d_in, const int* in_sizes, int n_in,
                              void* d_out, int out_size)
{
    const float* edges = (const float*)d_in[0];
    const float* feats = (const float*)d_in[1];
    const float* basis = (const float*)d_in[2];
    const float* W1    = (const float*)d_in[3];
    const float* b1    = (const float*)d_in[4];
    const float* W2    = (const float*)d_in[5];
    const float* b2    = (const float*)d_in[6];
    const float* W3    = (const float*)d_in[7];
    float* out = (float*)d_out;

    unsigned short *h1h, *h1l, *h2h, *h2l, *w2h, *w2l, *w3h, *w3l;
    float* rpp;
    cudaGetSymbolAddress((void**)&h1h, g_h1h);
    cudaGetSymbolAddress((void**)&h1l, g_h1l);
    cudaGetSymbolAddress((void**)&h2h, g_h2h);
    cudaGetSymbolAddress((void**)&h2l, g_h2l);
    cudaGetSymbolAddress((void**)&w2h, g_w2h);
    cudaGetSymbolAddress((void**)&w2l, g_w2l);
    cudaGetSymbolAddress((void**)&w3h, g_w3h);
    cudaGetSymbolAddress((void**)&w3l, g_w3l);
    cudaGetSymbolAddress((void**)&rpp, g_rp);

    cudaFuncSetAttribute(k_mma_gemm<true>,  cudaFuncAttributeMaxDynamicSharedMemorySize, SMEM_GEMM);
    cudaFuncSetAttribute(k_mma_gemm<false>, cudaFuncAttributeMaxDynamicSharedMemorySize, SMEM_GEMM);

    // 0) weight transpose + bf16 split
    k_prep_w<<<1024, 256>>>(W2, W3);

    // 1) h1 = gelu(edges @ W1 + b1) -> bf16 hi/lo
    k1_mlp1<<<E_TOTAL / 64, 256>>>(edges, W1, b1);

    // 2) h2 = gelu(h1 @ W2 + b2) -> bf16 hi/lo   (warp MMA)
    k_mma_gemm<true><<<dim3(MIDC / 128, E_TOTAL / 128), 256, SMEM_GEMM>>>(
        h1h, h1l, w2h, w2l, b2, h2h, h2l, nullptr, 0);

    // 3) rp = h2 @ W3[:, 768:1536] -> fp32       (warp MMA)
    k_mma_gemm<false><<<dim3(PCOLS / 128, E_TOTAL / 128), 256, SMEM_GEMM>>>(
        h2h, h2l, w3h, w3l, nullptr, nullptr, nullptr, rpp, PCOLS);

    // 4) out = rw @ (feats @ basis)
    k4_contract<<<E_TOTAL / 16, 256>>>(feats, basis, out);
}

// round 13
// speedup vs baseline: 3.4793x; 1.9804x over previous
#include <cuda_runtime.h>
#include <cuda_bf16.h>
#include <math.h>
#include <stdint.h>

typedef unsigned long long ull;

#define E_TOTAL   65536      // B*N*K = 2*1024*32
#define EDGE_DIM  32
#define MIDC      256
#define PCOLS     768        // SPLIT_SZ = NF*MI*MO
#define W3_LD     1536
#define W3_OFF    768        // SPLIT_OFF
#define NCHUNK    4
#define KC        64

// ---- scratch (static device globals; no allocations) ----
__device__ unsigned short g_h1h[(size_t)E_TOTAL * MIDC];
__device__ unsigned short g_h1l[(size_t)E_TOTAL * MIDC];
__device__ unsigned short g_h2h[(size_t)E_TOTAL * MIDC];
__device__ unsigned short g_h2l[(size_t)E_TOTAL * MIDC];
__device__ unsigned short g_w2h[256 * 256];                // W2^T [n][k]
__device__ unsigned short g_w2l[256 * 256];
__device__ unsigned short g_w3h[768 * 256];                // W3k^T [n][k]
__device__ unsigned short g_w3l[768 * 256];
__device__ float g_tmp[(size_t)E_TOTAL * 144];             // tmp[e][j=48][d=3], 37.7MB

__device__ __forceinline__ float gelu_exact(float x) {
    return 0.5f * x * (1.0f + erff(x * 0.70710678118654752f));
}
__device__ __forceinline__ void split2(float x, unsigned short& h, unsigned short& l) {
    __nv_bfloat16 bh = __float2bfloat16_rn(x);
    float r = x - __bfloat162float(bh);
    __nv_bfloat16 bl = __float2bfloat16_rn(r);
    h = __bfloat16_as_ushort(bh);
    l = __bfloat16_as_ushort(bl);
}

// ---- packed f32x2 helpers (k1) ----
__device__ __forceinline__ ull dup2(float x) {
    ull r; asm("mov.b64 %0, {%1, %1};" : "=l"(r) : "f"(x)); return r;
}
__device__ __forceinline__ ull fma2(ull a, ull b, ull c) {
    ull d; asm("fma.rn.f32x2 %0, %1, %2, %3;" : "=l"(d) : "l"(a), "l"(b), "l"(c)); return d;
}
__device__ __forceinline__ float2 unpack2(ull v) {
    float2 f; asm("mov.b64 {%0, %1}, %2;" : "=f"(f.x), "=f"(f.y) : "l"(v)); return f;
}

// ---- warp-MMA / async helpers (baseline PTX ISA on sm_103) ----
__device__ __forceinline__ uint32_t smem_u32(const void* p) {
    uint32_t a;
    asm("{ .reg .u64 t; cvta.to.shared.u64 t, %1; cvt.u32.u64 %0, t; }" : "=r"(a) : "l"(p));
    return a;
}
__device__ __forceinline__ void ldm4(uint32_t* r, uint32_t addr) {
    asm volatile("ldmatrix.sync.aligned.m8n8.x4.shared.b16 {%0,%1,%2,%3}, [%4];"
                 : "=r"(r[0]), "=r"(r[1]), "=r"(r[2]), "=r"(r[3]) : "r"(addr));
}
__device__ __forceinline__ void mma16816(float* c, const uint32_t* a, const uint32_t* b) {
    asm volatile(
        "mma.sync.aligned.m16n8k16.row.col.f32.bf16.bf16.f32 "
        "{%0,%1,%2,%3}, {%4,%5,%6,%7}, {%8,%9}, {%0,%1,%2,%3};"
        : "+f"(c[0]), "+f"(c[1]), "+f"(c[2]), "+f"(c[3])
        : "r"(a[0]), "r"(a[1]), "r"(a[2]), "r"(a[3]), "r"(b[0]), "r"(b[1]));
}
__device__ __forceinline__ void cpa16(uint32_t dst, const void* src) {
    asm volatile("cp.async.cg.shared.global [%0], [%1], 16;" :: "r"(dst), "l"(src));
}
#define CP_COMMIT() asm volatile("cp.async.commit_group;" ::: "memory")
__device__ __forceinline__ uint32_t sw128(uint32_t bo) {
    return bo ^ ((bo >> 3) & 0x70);
}

// ============================================================
// Kernel 0: transpose + split weights to bf16 hi/lo, K-major
// ============================================================
__global__ __launch_bounds__(256) void k_prep_w(
    const float* __restrict__ W2, const float* __restrict__ W3)
{
    int idx = blockIdx.x * 256 + threadIdx.x;
    if (idx < 256 * 256) {
        int k = idx >> 8, n = idx & 255;
        unsigned short h, l;
        split2(W2[k * 256 + n], h, l);
        g_w2h[n * 256 + k] = h;
        g_w2l[n * 256 + k] = l;
    } else {
        int j = idx - 256 * 256;
        int k = j / 768, n = j % 768;
        unsigned short h, l;
        split2(W3[k * W3_LD + W3_OFF + n], h, l);
        g_w3h[n * 256 + k] = h;
        g_w3l[n * 256 + k] = l;
    }
}

// ============================================================
// Kernel 1: h1 = gelu(edges[E,32] @ W1 + b1) -> bf16 hi/lo
// ============================================================
__global__ __launch_bounds__(256) void k1_mlp1(
    const float* __restrict__ edges, const float* __restrict__ W1,
    const float* __restrict__ b1)
{
    __shared__ float esT[32][64];
    __shared__ float W1s[32][256];
    const int tid = threadIdx.x;
    const long e0 = (long)blockIdx.x * 64;

    #pragma unroll
    for (int i = 0; i < 8; i++) {
        int flat = tid + i * 256;
        esT[flat & 31][flat >> 5] = edges[e0 * EDGE_DIM + flat];
    }
    #pragma unroll
    for (int i = 0; i < 32; i++) {
        int flat = tid + i * 256;
        W1s[flat >> 8][flat & 255] = W1[flat];
    }
    __syncthreads();

    const int m = tid;
    ull wd[EDGE_DIM];
    #pragma unroll
    for (int k = 0; k < EDGE_DIM; k++) wd[k] = dup2(W1s[k][m]);
    const ull binit = dup2(b1[m]);

    for (int p = 0; p < 32; p++) {
        ull acc = binit;
        #pragma unroll
        for (int k = 0; k < EDGE_DIM; k++) {
            ull a2 = reinterpret_cast<const ull*>(&esT[k][0])[p];
            acc = fma2(a2, wd[k], acc);
        }
        float2 v = unpack2(acc);
        unsigned short h, l;
        size_t o0 = (size_t)(e0 + 2 * p) * MIDC + m;
        split2(gelu_exact(v.x), h, l);
        g_h1h[o0] = h; g_h1l[o0] = l;
        split2(gelu_exact(v.y), h, l);
        g_h1h[o0 + MIDC] = h; g_h1l[o0 + MIDC] = l;
    }
}

// ============================================================
// Kernel T: tmp[e*144 + i*9 + z] = sum_din feats[e,i,din]*basis[e,din,z]
// ============================================================
__global__ __launch_bounds__(256) void k_tmp(
    const float* __restrict__ feats, const float* __restrict__ basis)
{
    int idx = blockIdx.x * 256 + threadIdx.x;   // E*144
    int e = idx / 144;
    int f = idx % 144;
    int i = f / 9;
    int z = f % 9;
    const float* fp = feats + (size_t)e * 48 + i * 3;
    const float* bp = basis + (size_t)e * 27 + z;
    float v = fp[0] * bp[0] + fp[1] * bp[9] + fp[2] * bp[18];
    g_tmp[idx] = v;
}

// ============================================================
// bf16-split warp-MMA GEMM, cp.async double-buffered.
//   C[128e x NTILE n] tile, K=256 in 4 chunks of 64, swizzled 128B rows.
//   D = Ah@Bh + Ah@Bl + Al@Bh
//   GELU: C = gelu(D+bias) -> bf16 hi/lo.  FUSE: out[e,o,d] += D*tmp (k4 fused)
// 8 warps (4m x 2n), warp tile 32 x NTILE/2.
// ============================================================
template <int NTILE, bool GELU, bool FUSE>
__global__ __launch_bounds__(256) void k_mma_gemm(
    const unsigned short* __restrict__ Ah, const unsigned short* __restrict__ Al,
    const unsigned short* __restrict__ Wh, const unsigned short* __restrict__ Wl,
    const float* __restrict__ bias,
    unsigned short* __restrict__ Ch, unsigned short* __restrict__ Cl,
    const float* __restrict__ tmpg, float* __restrict__ outg)
{
    constexpr int SA    = 128 * 128;           // one A tile (bytes)
    constexpr int SB    = NTILE * 128;         // one B tile (bytes)
    constexpr int CHUNK = 2 * SA + 2 * SB;     // AH AL BH BL
    constexpr int NG    = NTILE / 16;          // n8-groups per warp
    constexpr int NP    = NTILE / 32;          // 16-col B ldmatrix groups

    extern __shared__ char sm[];
    const uint32_t smb = smem_u32(sm);
    const int tid = threadIdx.x;
    const int wid = tid >> 5;
    const int l   = tid & 31;
    const int wm  = wid >> 1;
    const int wn  = wid & 1;
    const long e0 = (long)blockIdx.y * 128;
    const int n0  = blockIdx.x * NTILE;
    float* bias_s = reinterpret_cast<float*>(sm + 2 * CHUNK);

    if (GELU && tid < NTILE) bias_s[tid] = bias[n0 + tid];

    // ---- staging geometry (16B segs, swizzled) ----
    const int srow = tid >> 1;                 // A row pair-owner: 2 threads/row
    const int sseg = tid & 1;                  // 4 segs each
    const size_t gA = (size_t)(e0 + srow) * 256 + sseg * 32;
    const uint32_t swA[4] = {
        sw128((uint32_t)srow * 128 + sseg * 64 + 0),
        sw128((uint32_t)srow * 128 + sseg * 64 + 16),
        sw128((uint32_t)srow * 128 + sseg * 64 + 32),
        sw128((uint32_t)srow * 128 + sseg * 64 + 48)};

    auto stage = [&](int c, int buf) {
        const int k0 = c * KC;
        const uint32_t base = smb + buf * CHUNK;
        #pragma unroll
        for (int i = 0; i < 4; i++) {
            cpa16(base + swA[i],      Ah + gA + k0 + i * 8);
            cpa16(base + SA + swA[i], Al + gA + k0 + i * 8);
        }
        // B: NTILE rows * 8 segs
        #pragma unroll
        for (int i = 0; i < NTILE * 8 / 256; i++) {
            int s = tid + i * 256;
            int row = s >> 3, sc = s & 7;
            uint32_t so = sw128((uint32_t)row * 128 + sc * 16);
            const size_t gB = (size_t)(n0 + row) * 256 + k0 + sc * 8;
            cpa16(base + 2 * SA + so,      Wh + gB);
            cpa16(base + 2 * SA + SB + so, Wl + gB);
        }
    };

    // ---- ldmatrix per-thread row/koff (byte offsets before swizzle) ----
    const uint32_t aro  = (uint32_t)(wm * 32 + (l & 15)) * 128 + ((l >> 4) * 16);
    const uint32_t aro1 = aro + 16 * 128;
    const int brow_in16 = ((l & 16) >> 1) + (l & 7);
    const uint32_t bko  = (l & 8) ? 16u : 0u;
    uint32_t bro[NP];
    #pragma unroll
    for (int p = 0; p < NP; p++)
        bro[p] = (uint32_t)(wn * (NTILE / 2) + p * 16 + brow_in16) * 128 + bko;

    float acc[2][NG][4];
    #pragma unroll
    for (int mi = 0; mi < 2; mi++)
        #pragma unroll
        for (int ng = 0; ng < NG; ng++)
            #pragma unroll
            for (int t = 0; t < 4; t++) acc[mi][ng][t] = 0.0f;

    stage(0, 0);
    CP_COMMIT();

    for (int c = 0; c < NCHUNK; c++) {
        if (c < NCHUNK - 1) {
            stage(c + 1, (c + 1) & 1);
            CP_COMMIT();
            asm volatile("cp.async.wait_group 1;" ::: "memory");
        } else {
            asm volatile("cp.async.wait_group 0;" ::: "memory");
        }
        __syncthreads();

        const uint32_t base = smb + (c & 1) * CHUNK;
        #pragma unroll
        for (int ks = 0; ks < 4; ks++) {
            const uint32_t kb = ks * 32;
            uint32_t ahf[2][4], alf[2][4];
            ldm4(ahf[0], base + sw128(aro + kb));
            ldm4(ahf[1], base + sw128(aro1 + kb));
            ldm4(alf[0], base + SA + sw128(aro + kb));
            ldm4(alf[1], base + SA + sw128(aro1 + kb));
            #pragma unroll
            for (int p = 0; p < NP; p++) {
                uint32_t bhf[4], blf[4];
                ldm4(bhf, base + 2 * SA + sw128(bro[p] + kb));
                ldm4(blf, base + 2 * SA + SB + sw128(bro[p] + kb));
                #pragma unroll
                for (int mi = 0; mi < 2; mi++) {
                    mma16816(acc[mi][2 * p],     ahf[mi], bhf);
                    mma16816(acc[mi][2 * p + 1], ahf[mi], bhf + 2);
                    mma16816(acc[mi][2 * p],     ahf[mi], blf);
                    mma16816(acc[mi][2 * p + 1], ahf[mi], blf + 2);
                    mma16816(acc[mi][2 * p],     alf[mi], bhf);
                    mma16816(acc[mi][2 * p + 1], alf[mi], bhf + 2);
                }
            }
        }
        __syncthreads();
    }

    if (GELU) {
        // ---- epilogue: gelu(D+bias) -> bf16 hi/lo ----
        const int crow = wm * 32 + (l >> 2);
        const int ccol = wn * (NTILE / 2) + 2 * (l & 3);
        #pragma unroll
        for (int mi = 0; mi < 2; mi++) {
            #pragma unroll
            for (int ng = 0; ng < NG; ng++) {
                const int col = ccol + ng * 8;
                const float* cf = acc[mi][ng];
                #pragma unroll
                for (int half = 0; half < 2; half++) {
                    const long e = e0 + crow + mi * 16 + half * 8;
                    float x0 = gelu_exact(cf[2 * half + 0] + bias_s[col]);
                    float x1 = gelu_exact(cf[2 * half + 1] + bias_s[col + 1]);
                    unsigned short h0, l0, h1, l1;
                    split2(x0, h0, l0);
                    split2(x1, h1, l1);
                    *reinterpret_cast<uint32_t*>(Ch + (size_t)e * MIDC + n0 + col) =
                        (uint32_t)h0 | ((uint32_t)h1 << 16);
                    *reinterpret_cast<uint32_t*>(Cl + (size_t)e * MIDC + n0 + col) =
                        (uint32_t)l0 | ((uint32_t)l1 << 16);
                }
            }
        }
    }
    if (FUSE) {
        // ---- fused k4: stage tmp[e0..e0+127][144] into smem, contract ----
        float* tsm = reinterpret_cast<float*>(sm);
        {
            const float4* tg = reinterpret_cast<const float4*>(tmpg + e0 * 144);
            float4* ts4 = reinterpret_cast<float4*>(sm);
            #pragma unroll
            for (int i = 0; i < 18; i++) ts4[tid + i * 256] = tg[tid + i * 256];
        }
        __syncthreads();

        // partial out over this thread's c-frag entries
        float pout[4][3];
        #pragma unroll
        for (int r = 0; r < 4; r++)
            #pragma unroll
            for (int d = 0; d < 3; d++) pout[r][d] = 0.0f;

        const int rbase = wm * 32 + (l >> 2);
        #pragma unroll
        for (int mi = 0; mi < 2; mi++) {
            #pragma unroll
            for (int half = 0; half < 2; half++) {
                const int el = rbase + mi * 16 + half * 8;
                const float* te = tsm + el * 144;
                #pragma unroll
                for (int ng = 0; ng < NG; ng++) {
                    #pragma unroll
                    for (int t = 0; t < 2; t++) {
                        const int j = 2 * (l & 3) + ng * 8 + t;
                        const float rp = acc[mi][ng][2 * half + t];
                        pout[mi * 2 + half][0] = fmaf(rp, te[j * 3 + 0], pout[mi * 2 + half][0]);
                        pout[mi * 2 + half][1] = fmaf(rp, te[j * 3 + 1], pout[mi * 2 + half][1]);
                        pout[mi * 2 + half][2] = fmaf(rp, te[j * 3 + 2], pout[mi * 2 + half][2]);
                    }
                }
            }
        }
        // reduce across the 4 lanes sharing rows (l&3)
        #pragma unroll
        for (int r = 0; r < 4; r++)
            #pragma unroll
            for (int d = 0; d < 3; d++) {
                float v = pout[r][d];
                v += __shfl_xor_sync(0xFFFFFFFFu, v, 1);
                v += __shfl_xor_sync(0xFFFFFFFFu, v, 2);
                pout[r][d] = v;
            }
        if ((l & 3) == 0) {
            const int og = blockIdx.x * 2 + wn;   // NTILE=96 -> 2 o-groups/CTA
            #pragma unroll
            for (int mi = 0; mi < 2; mi++)
                #pragma unroll
                for (int half = 0; half < 2; half++) {
                    const long e = e0 + rbase + mi * 16 + half * 8;
                    float* op = outg + e * 48 + og * 3;
                    op[0] = pout[mi * 2 + half][0];
                    op[1] = pout[mi * 2 + half][1];
                    op[2] = pout[mi * 2 + half][2];
                }
        }
    }
}

// ============================================================
extern "C" void kernel_launch(void* const* d_in, const int* in_sizes, int n_in,
                              void* d_out, int out_size)
{
    const float* edges = (const float*)d_in[0];
    const float* feats = (const float*)d_in[1];
    const float* basis = (const float*)d_in[2];
    const float* W1    = (const float*)d_in[3];
    const float* b1    = (const float*)d_in[4];
    const float* W2    = (const float*)d_in[5];
    const float* b2    = (const float*)d_in[6];
    const float* W3    = (const float*)d_in[7];
    float* out = (float*)d_out;

    unsigned short *h1h, *h1l, *h2h, *h2l, *w2h, *w2l, *w3h, *w3l;
    float* tmpp;
    cudaGetSymbolAddress((void**)&h1h, g_h1h);
    cudaGetSymbolAddress((void**)&h1l, g_h1l);
    cudaGetSymbolAddress((void**)&h2h, g_h2h);
    cudaGetSymbolAddress((void**)&h2l, g_h2l);
    cudaGetSymbolAddress((void**)&w2h, g_w2h);
    cudaGetSymbolAddress((void**)&w2l, g_w2l);
    cudaGetSymbolAddress((void**)&w3h, g_w3h);
    cudaGetSymbolAddress((void**)&w3l, g_w3l);
    cudaGetSymbolAddress((void**)&tmpp, g_tmp);

    // smem: GEMM2 (NTILE=128): 2*(2*16384+2*16384) + 512 = 131584
    //       GEMM3 (NTILE=96) : 2*(2*16384+2*12288) = 114688 (>= 73728 tmp slice)
    const int SM2 = 2 * (2 * 16384 + 2 * 16384) + 512;
    const int SM3 = 2 * (2 * 16384 + 2 * 12288);
    cudaFuncSetAttribute((const void*)k_mma_gemm<128, true, false>,
                         cudaFuncAttributeMaxDynamicSharedMemorySize, SM2);
    cudaFuncSetAttribute((const void*)k_mma_gemm<96, false, true>,
                         cudaFuncAttributeMaxDynamicSharedMemorySize, SM3);

    // 0) weight transpose + bf16 split
    k_prep_w<<<1024, 256>>>(W2, W3);

    // 1) h1 = gelu(edges @ W1 + b1) -> bf16 hi/lo
    k1_mlp1<<<E_TOTAL / 64, 256>>>(edges, W1, b1);

    // T) tmp = feats @ basis  (37.7MB)
    k_tmp<<<E_TOTAL * 144 / 256, 256>>>(feats, basis);

    // 2) h2 = gelu(h1 @ W2 + b2) -> bf16 hi/lo
    k_mma_gemm<128, true, false><<<dim3(MIDC / 128, E_TOTAL / 128), 256, SM2>>>(
        h1h, h1l, w2h, w2l, b2, h2h, h2l, nullptr, nullptr);

    // 3) out = (h2 @ W3k) contracted with tmp  (rp never hits DRAM)
    k_mma_gemm<96, false, true><<<dim3(PCOLS / 96, E_TOTAL / 128), 256, SM3>>>(
        h2h, h2l, w3h, w3l, nullptr, nullptr, nullptr, tmpp, out);

    // no k4 — fused into GEMM3 epilogue
}